// round 1
// baseline (speedup 1.0000x reference)
#include <cuda_runtime.h>
#include <cuda_bf16.h>
#include <math.h>

// ---------------------------------------------------------------------------
// Problem constants
// ---------------------------------------------------------------------------
#define DIM   1024
#define HID   4096
#define NH    16
#define DH    64
#define N0    1370
#define B0    4
#define N1    257
#define B1    8
#define T0    (B0 * N0)          // 5480
#define T1    (B1 * N1)          // 2056
#define TT    (T0 + T1)          // 7536 tokens
#define LN_EPS 1e-5f

// ---------------------------------------------------------------------------
// Scratch (device globals; allocation inside kernel_launch is forbidden)
// ---------------------------------------------------------------------------
__device__ float g_X  [(size_t)TT * DIM];     // packed input
__device__ float g_Y  [(size_t)TT * DIM];     // LN output (reused for LN1 and LN2)
__device__ float g_QKV[(size_t)TT * 3 * DIM]; // qkv projection
__device__ float g_ATT[(size_t)TT * DIM];     // attention output (heads concat)
__device__ float g_H  [(size_t)TT * DIM];     // post-attention residual
__device__ float g_G  [(size_t)TT * HID];     // gelu(fc1) output

// ---------------------------------------------------------------------------
// Pack kernel: concatenate x0, x1 rows into g_X (float4 copy)
// ---------------------------------------------------------------------------
__global__ void copy4_kernel(const float* __restrict__ src, float* __restrict__ dst, int n4) {
    int i = blockIdx.x * blockDim.x + threadIdx.x;
    if (i < n4) ((float4*)dst)[i] = ((const float4*)src)[i];
}

// ---------------------------------------------------------------------------
// LayerNorm: one 256-thread block per 1024-wide row
// ---------------------------------------------------------------------------
__global__ void __launch_bounds__(256) ln_kernel(
    const float* __restrict__ in, const float* __restrict__ gm,
    const float* __restrict__ bt, float* __restrict__ out)
{
    int row = blockIdx.x;
    int tid = threadIdx.x;
    const float4 v = *(const float4*)(in + (size_t)row * DIM + tid * 4);

    float s = v.x + v.y + v.z + v.w;
    float q = v.x * v.x + v.y * v.y + v.z * v.z + v.w * v.w;
    #pragma unroll
    for (int o = 16; o > 0; o >>= 1) {
        s += __shfl_xor_sync(0xffffffffu, s, o);
        q += __shfl_xor_sync(0xffffffffu, q, o);
    }
    __shared__ float ss[8], qq[8];
    if ((tid & 31) == 0) { ss[tid >> 5] = s; qq[tid >> 5] = q; }
    __syncthreads();
    float st = 0.f, qt = 0.f;
    #pragma unroll
    for (int i = 0; i < 8; i++) { st += ss[i]; qt += qq[i]; }

    float mean = st * (1.0f / DIM);
    float var  = qt * (1.0f / DIM) - mean * mean;
    float rstd = rsqrtf(var + LN_EPS);

    float4 g4 = *(const float4*)(gm + tid * 4);
    float4 b4 = *(const float4*)(bt + tid * 4);
    float4 o;
    o.x = (v.x - mean) * rstd * g4.x + b4.x;
    o.y = (v.y - mean) * rstd * g4.y + b4.y;
    o.z = (v.z - mean) * rstd * g4.z + b4.z;
    o.w = (v.w - mean) * rstd * g4.w + b4.w;
    *(float4*)(out + (size_t)row * DIM + tid * 4) = o;
}

// ---------------------------------------------------------------------------
// SGEMM: C = epilogue(A[M,K] @ B[K,N] + bias)
//   EPI 0: + bias
//   EPI 1: res + ls * (acc + bias)     (residual + layerscale)
//   EPI 2: gelu_exact(acc + bias)
// 128x128 block tile, BK=16, 256 threads, 8x8 per thread.
// ---------------------------------------------------------------------------
#define BM 128
#define BN 128
#define BK 16
#define TM 8
#define TN 8

__device__ __forceinline__ float gelu_exact(float x) {
    return 0.5f * x * (1.0f + erff(x * 0.70710678118654752440f));
}

template<int EPI>
__global__ void __launch_bounds__(256) sgemm_kernel(
    const float* __restrict__ A, const float* __restrict__ B,
    const float* __restrict__ bias, const float* __restrict__ res,
    const float* __restrict__ ls, float* __restrict__ C,
    int M, int N, int K)
{
    __shared__ float As[BK][BM + 4];   // A stored transposed: As[k][m]
    __shared__ float Bs[BK][BN];

    const int tid = threadIdx.x;
    const int tx  = tid & 15;          // 16 col groups
    const int ty  = tid >> 4;          // 16 row groups
    const int rowBase = blockIdx.y * BM;
    const int colBase = blockIdx.x * BN;

    const int aRow0 = tid >> 2;                 // 0..63, +64 for second load
    const int aCol  = (tid & 3) * 4;            // 0,4,8,12
    const int bRow0 = tid >> 5;                 // 0..7, +8 for second load
    const int bCol  = (tid & 31) * 4;           // 0..124

    float acc[TM][TN] = {};

    for (int k0 = 0; k0 < K; k0 += BK) {
        // load A tile (transposed into smem)
        #pragma unroll
        for (int i = 0; i < 2; i++) {
            int r  = aRow0 + i * 64;
            int gr = rowBase + r;
            float4 v = make_float4(0.f, 0.f, 0.f, 0.f);
            if (gr < M) v = *(const float4*)&A[(size_t)gr * K + k0 + aCol];
            As[aCol + 0][r] = v.x;
            As[aCol + 1][r] = v.y;
            As[aCol + 2][r] = v.z;
            As[aCol + 3][r] = v.w;
        }
        // load B tile
        #pragma unroll
        for (int i = 0; i < 2; i++) {
            int r = bRow0 + i * 8;
            *(float4*)&Bs[r][bCol] = *(const float4*)&B[(size_t)(k0 + r) * N + colBase + bCol];
        }
        __syncthreads();

        #pragma unroll
        for (int kk = 0; kk < BK; kk++) {
            float a[TM], b[TN];
            float4 a0 = *(const float4*)&As[kk][ty * TM];
            float4 a1 = *(const float4*)&As[kk][ty * TM + 4];
            float4 b0 = *(const float4*)&Bs[kk][tx * TN];
            float4 b1 = *(const float4*)&Bs[kk][tx * TN + 4];
            a[0]=a0.x; a[1]=a0.y; a[2]=a0.z; a[3]=a0.w;
            a[4]=a1.x; a[5]=a1.y; a[6]=a1.z; a[7]=a1.w;
            b[0]=b0.x; b[1]=b0.y; b[2]=b0.z; b[3]=b0.w;
            b[4]=b1.x; b[5]=b1.y; b[6]=b1.z; b[7]=b1.w;
            #pragma unroll
            for (int i = 0; i < TM; i++)
                #pragma unroll
                for (int j = 0; j < TN; j++)
                    acc[i][j] += a[i] * b[j];
        }
        __syncthreads();
    }

    // epilogue
    #pragma unroll
    for (int i = 0; i < TM; i++) {
        int gr = rowBase + ty * TM + i;
        if (gr >= M) break;
        #pragma unroll
        for (int j = 0; j < TN; j++) {
            int gc = colBase + tx * TN + j;
            float v = acc[i][j] + __ldg(&bias[gc]);
            if (EPI == 1) v = __ldg(&res[(size_t)gr * N + gc]) + __ldg(&ls[gc]) * v;
            else if (EPI == 2) v = gelu_exact(v);
            C[(size_t)gr * N + gc] = v;
        }
    }
}

// ---------------------------------------------------------------------------
// Flash attention: one CTA per (q-block of 64, head). Online softmax over
// 64-key tiles. Per-sample full attention (block-diagonal mask).
// Layout of QKV row: [q(1024) | k(1024) | v(1024)], head h occupies cols h*64..
// ---------------------------------------------------------------------------
#define QB0 22                       // ceil(1370/64)
#define QB1 5                        // ceil(257/64)
#define NQB (B0 * QB0 + B1 * QB1)    // 128 q-blocks total

#define AT_QS   (64 * 68)
#define AT_PS   (64 * 72)
#define ATTN_SMEM_FLOATS (3 * AT_QS + AT_PS + 3 * 64)
#define ATTN_SMEM_BYTES  (ATTN_SMEM_FLOATS * 4)

__global__ void __launch_bounds__(256) attn_kernel(
    const float* __restrict__ QKV, float* __restrict__ ATT)
{
    extern __shared__ float sm[];
    float* Qs = sm;                    // [d][q], stride 68
    float* Ks = Qs + AT_QS;            // [d][k], stride 68
    float* Vs = Ks + AT_QS;            // [k][d], stride 68
    float* Ps = Vs + AT_QS;            // [q][k], stride 72
    float* m_s    = Ps + AT_PS;
    float* l_s    = m_s + 64;
    float* corr_s = l_s + 64;

    const int tid = threadIdx.x;
    const int h   = blockIdx.y;
    const int qb  = blockIdx.x;

    int tok0, n, q0;
    if (qb < B0 * QB0) {
        int s = qb / QB0;  q0 = (qb % QB0) * 64;  n = N0;  tok0 = s * N0;
    } else {
        int t = qb - B0 * QB0;
        int s = t / QB1;   q0 = (t % QB1) * 64;   n = N1;  tok0 = T0 + s * N1;
    }

    const int tx = tid & 15;
    const int ty = tid >> 4;

    if (tid < 64) { m_s[tid] = -1e30f; l_s[tid] = 0.f; }

    // load Q tile (transposed, scaled by dh^-0.5 = 0.125)
    {
        int q  = tid >> 2;
        int d0 = (tid & 3) * 16;
        int gq = q0 + q;
        const float* src = QKV + (size_t)(tok0 + ((gq < n) ? gq : 0)) * (3 * DIM) + h * DH + d0;
        bool valid = (gq < n);
        #pragma unroll
        for (int j = 0; j < 16; j++)
            Qs[(d0 + j) * 68 + q] = valid ? src[j] * 0.125f : 0.f;
    }
    __syncthreads();

    float acc_o[4][4] = {};

    const int nkt = (n + 63) >> 6;
    for (int kt = 0; kt < nkt; kt++) {
        const int kbase = kt << 6;

        // ---- load K (transposed) and V tiles ----
        {
            int k  = tid >> 2;
            int d0 = (tid & 3) * 16;
            int gk = kbase + k;
            bool valid = (gk < n);
            const float* kp = QKV + (size_t)(tok0 + (valid ? gk : 0)) * (3 * DIM) + DIM     + h * DH + d0;
            const float* vp = QKV + (size_t)(tok0 + (valid ? gk : 0)) * (3 * DIM) + 2 * DIM + h * DH + d0;
            if (valid) {
                #pragma unroll
                for (int j = 0; j < 16; j += 4) {
                    float4 kv = *(const float4*)(kp + j);
                    Ks[(d0 + j + 0) * 68 + k] = kv.x;
                    Ks[(d0 + j + 1) * 68 + k] = kv.y;
                    Ks[(d0 + j + 2) * 68 + k] = kv.z;
                    Ks[(d0 + j + 3) * 68 + k] = kv.w;
                    *(float4*)(Vs + k * 68 + d0 + j) = *(const float4*)(vp + j);
                }
            } else {
                #pragma unroll
                for (int j = 0; j < 16; j++) Ks[(d0 + j) * 68 + k] = 0.f;
                #pragma unroll
                for (int j = 0; j < 16; j += 4)
                    *(float4*)(Vs + k * 68 + d0 + j) = make_float4(0.f, 0.f, 0.f, 0.f);
            }
        }
        __syncthreads();

        // ---- S = Q @ K^T (4x4 per thread) ----
        float acc_s[4][4] = {};
        #pragma unroll 4
        for (int d = 0; d < 64; d++) {
            float4 a4 = *(const float4*)(Qs + d * 68 + ty * 4);
            float4 b4 = *(const float4*)(Ks + d * 68 + tx * 4);
            float a[4] = {a4.x, a4.y, a4.z, a4.w};
            float b[4] = {b4.x, b4.y, b4.z, b4.w};
            #pragma unroll
            for (int i = 0; i < 4; i++)
                #pragma unroll
                for (int j = 0; j < 4; j++)
                    acc_s[i][j] += a[i] * b[j];
        }
        #pragma unroll
        for (int i = 0; i < 4; i++)
            *(float4*)(Ps + (ty * 4 + i) * 72 + tx * 4) =
                make_float4(acc_s[i][0], acc_s[i][1], acc_s[i][2], acc_s[i][3]);
        __syncthreads();

        // ---- online softmax bookkeeping: 4 threads per row ----
        {
            int row = tid >> 2, sub = tid & 3;
            float vals[16];
            float mx = -1e30f;
            #pragma unroll
            for (int j = 0; j < 16; j++) {
                int k = sub * 16 + j;
                float sv = Ps[row * 72 + k];
                if (kbase + k >= n) sv = -1e30f;
                vals[j] = sv;
                mx = fmaxf(mx, sv);
            }
            mx = fmaxf(mx, __shfl_xor_sync(0xffffffffu, mx, 1));
            mx = fmaxf(mx, __shfl_xor_sync(0xffffffffu, mx, 2));
            float m_old = m_s[row];
            float m_new = fmaxf(m_old, mx);
            float ssum = 0.f;
            #pragma unroll
            for (int j = 0; j < 16; j++) {
                float p = expf(vals[j] - m_new);
                Ps[row * 72 + sub * 16 + j] = p;
                ssum += p;
            }
            ssum += __shfl_xor_sync(0xffffffffu, ssum, 1);
            ssum += __shfl_xor_sync(0xffffffffu, ssum, 2);
            if (sub == 0) {
                float corr = expf(m_old - m_new);
                corr_s[row] = corr;
                m_s[row]    = m_new;
                l_s[row]    = l_s[row] * corr + ssum;
            }
        }
        __syncthreads();

        // ---- rescale accumulators, O += P @ V ----
        #pragma unroll
        for (int i = 0; i < 4; i++) {
            float c = corr_s[ty * 4 + i];
            #pragma unroll
            for (int j = 0; j < 4; j++) acc_o[i][j] *= c;
        }
        #pragma unroll 4
        for (int k = 0; k < 64; k++) {
            float4 b4 = *(const float4*)(Vs + k * 68 + tx * 4);
            float b[4] = {b4.x, b4.y, b4.z, b4.w};
            float a[4];
            #pragma unroll
            for (int i = 0; i < 4; i++) a[i] = Ps[(ty * 4 + i) * 72 + k];
            #pragma unroll
            for (int i = 0; i < 4; i++)
                #pragma unroll
                for (int j = 0; j < 4; j++)
                    acc_o[i][j] += a[i] * b[j];
        }
        __syncthreads();
    }

    // ---- finalize and write ----
    #pragma unroll
    for (int i = 0; i < 4; i++) {
        int gq = q0 + ty * 4 + i;
        if (gq < n) {
            float inv = 1.0f / l_s[ty * 4 + i];
            float4 o = make_float4(acc_o[i][0] * inv, acc_o[i][1] * inv,
                                   acc_o[i][2] * inv, acc_o[i][3] * inv);
            *(float4*)(ATT + (size_t)(tok0 + gq) * DIM + h * DH + tx * 4) = o;
        }
    }
}

// ---------------------------------------------------------------------------
// Launch
// ---------------------------------------------------------------------------
extern "C" void kernel_launch(void* const* d_in, const int* in_sizes, int n_in,
                              void* d_out, int out_size)
{
    const float* x0     = (const float*)d_in[0];
    const float* x1     = (const float*)d_in[1];
    const float* ln1_g  = (const float*)d_in[2];
    const float* ln1_b  = (const float*)d_in[3];
    const float* qkv_w  = (const float*)d_in[4];
    const float* qkv_b  = (const float*)d_in[5];
    const float* proj_w = (const float*)d_in[6];
    const float* proj_b = (const float*)d_in[7];
    const float* ls1    = (const float*)d_in[8];
    const float* ln2_g  = (const float*)d_in[9];
    const float* ln2_b  = (const float*)d_in[10];
    const float* fc1_w  = (const float*)d_in[11];
    const float* fc1_b  = (const float*)d_in[12];
    const float* fc2_w  = (const float*)d_in[13];
    const float* fc2_b  = (const float*)d_in[14];
    const float* ls2    = (const float*)d_in[15];

    void *pX, *pY, *pQKV, *pATT, *pH, *pG;
    cudaGetSymbolAddress(&pX,   g_X);
    cudaGetSymbolAddress(&pY,   g_Y);
    cudaGetSymbolAddress(&pQKV, g_QKV);
    cudaGetSymbolAddress(&pATT, g_ATT);
    cudaGetSymbolAddress(&pH,   g_H);
    cudaGetSymbolAddress(&pG,   g_G);
    float* X   = (float*)pX;
    float* Y   = (float*)pY;
    float* QKV = (float*)pQKV;
    float* ATT = (float*)pATT;
    float* H   = (float*)pH;
    float* G   = (float*)pG;
    float* OUT = (float*)d_out;

    const int mTiles = (TT + BM - 1) / BM;   // 59

    // 1. pack x0 | x1 -> X
    {
        int n4a = T0 * DIM / 4, n4b = T1 * DIM / 4;
        copy4_kernel<<<(n4a + 255) / 256, 256>>>(x0, X, n4a);
        copy4_kernel<<<(n4b + 255) / 256, 256>>>(x1, X + (size_t)T0 * DIM, n4b);
    }

    // 2. LN1: Y = LN(X)
    ln_kernel<<<TT, 256>>>(X, ln1_g, ln1_b, Y);

    // 3. QKV = Y @ qkv_w + qkv_b
    sgemm_kernel<0><<<dim3(3 * DIM / BN, mTiles), 256>>>(
        Y, qkv_w, qkv_b, nullptr, nullptr, QKV, TT, 3 * DIM, DIM);

    // 4. attention -> ATT
    cudaFuncSetAttribute(attn_kernel, cudaFuncAttributeMaxDynamicSharedMemorySize,
                         ATTN_SMEM_BYTES);
    attn_kernel<<<dim3(NQB, NH), 256, ATTN_SMEM_BYTES>>>(QKV, ATT);

    // 5. H = X + ls1 * (ATT @ proj_w + proj_b)
    sgemm_kernel<1><<<dim3(DIM / BN, mTiles), 256>>>(
        ATT, proj_w, proj_b, X, ls1, H, TT, DIM, DIM);

    // 6. LN2: Y = LN(H)
    ln_kernel<<<TT, 256>>>(H, ln2_g, ln2_b, Y);

    // 7. G = gelu(Y @ fc1_w + fc1_b)
    sgemm_kernel<2><<<dim3(HID / BN, mTiles), 256>>>(
        Y, fc1_w, fc1_b, nullptr, nullptr, G, TT, HID, DIM);

    // 8. OUT = H + ls2 * (G @ fc2_w + fc2_b)
    sgemm_kernel<1><<<dim3(DIM / BN, mTiles), 256>>>(
        G, fc2_w, fc2_b, H, ls2, OUT, TT, DIM, HID);
}

// round 2
// speedup vs baseline: 2.8689x; 2.8689x over previous
#include <cuda_runtime.h>
#include <cuda_bf16.h>
#include <math.h>

// ---------------------------------------------------------------------------
// Problem constants
// ---------------------------------------------------------------------------
#define DIM   1024
#define HID   4096
#define NH    16
#define DH    64
#define N0    1370
#define B0    4
#define N1    257
#define B1    8
#define T0    (B0 * N0)          // 5480
#define T1    (B1 * N1)          // 2056
#define TT    (T0 + T1)          // 7536 tokens
#define LN_EPS 1e-5f

// ---------------------------------------------------------------------------
// Scratch (device globals; allocation inside kernel_launch is forbidden)
// ---------------------------------------------------------------------------
__device__ float g_X  [(size_t)TT * DIM];          // packed input (fp32)
__device__ float g_QKV[(size_t)TT * 3 * DIM];      // qkv projection (fp32)
__device__ float g_H  [(size_t)TT * DIM];          // post-attention residual (fp32)
__device__ __nv_bfloat16 g_Yb  [(size_t)TT * DIM]; // LN output (bf16)
__device__ __nv_bfloat16 g_ATTb[(size_t)TT * DIM]; // attention output (bf16)
__device__ __nv_bfloat16 g_Gb  [(size_t)TT * HID]; // gelu(fc1) (bf16)
// bf16 weights: qkv | proj | fc1 | fc2
#define WOFF_QKV  0
#define WOFF_PROJ ((size_t)DIM * 3 * DIM)
#define WOFF_FC1  (WOFF_PROJ + (size_t)DIM * DIM)
#define WOFF_FC2  (WOFF_FC1 + (size_t)DIM * HID)
#define W_TOTAL   (WOFF_FC2 + (size_t)HID * DIM)
__device__ __nv_bfloat16 g_Wb[W_TOTAL];

// ---------------------------------------------------------------------------
// Elementwise kernels
// ---------------------------------------------------------------------------
__global__ void copy4_kernel(const float* __restrict__ src, float* __restrict__ dst, int n4) {
    int i = blockIdx.x * blockDim.x + threadIdx.x;
    if (i < n4) ((float4*)dst)[i] = ((const float4*)src)[i];
}

// fp32 -> bf16 (4 elems/thread)
__global__ void f2b_kernel(const float* __restrict__ src, __nv_bfloat16* __restrict__ dst, int n4) {
    int i = blockIdx.x * blockDim.x + threadIdx.x;
    if (i < n4) {
        float4 v = ((const float4*)src)[i];
        __nv_bfloat162 p0 = __floats2bfloat162_rn(v.x, v.y);
        __nv_bfloat162 p1 = __floats2bfloat162_rn(v.z, v.w);
        uint2 u;
        u.x = *(unsigned int*)&p0;
        u.y = *(unsigned int*)&p1;
        ((uint2*)dst)[i] = u;
    }
}

// ---------------------------------------------------------------------------
// LayerNorm: one 256-thread block per 1024-wide row, bf16 output
// ---------------------------------------------------------------------------
__global__ void __launch_bounds__(256) ln_kernel(
    const float* __restrict__ in, const float* __restrict__ gm,
    const float* __restrict__ bt, __nv_bfloat16* __restrict__ out)
{
    int row = blockIdx.x;
    int tid = threadIdx.x;
    const float4 v = *(const float4*)(in + (size_t)row * DIM + tid * 4);

    float s = v.x + v.y + v.z + v.w;
    float q = v.x * v.x + v.y * v.y + v.z * v.z + v.w * v.w;
    #pragma unroll
    for (int o = 16; o > 0; o >>= 1) {
        s += __shfl_xor_sync(0xffffffffu, s, o);
        q += __shfl_xor_sync(0xffffffffu, q, o);
    }
    __shared__ float ss[8], qq[8];
    if ((tid & 31) == 0) { ss[tid >> 5] = s; qq[tid >> 5] = q; }
    __syncthreads();
    float st = 0.f, qt = 0.f;
    #pragma unroll
    for (int i = 0; i < 8; i++) { st += ss[i]; qt += qq[i]; }

    float mean = st * (1.0f / DIM);
    float var  = qt * (1.0f / DIM) - mean * mean;
    float rstd = rsqrtf(var + LN_EPS);

    float4 g4 = *(const float4*)(gm + tid * 4);
    float4 b4 = *(const float4*)(bt + tid * 4);
    __nv_bfloat162 p0 = __floats2bfloat162_rn((v.x - mean) * rstd * g4.x + b4.x,
                                              (v.y - mean) * rstd * g4.y + b4.y);
    __nv_bfloat162 p1 = __floats2bfloat162_rn((v.z - mean) * rstd * g4.z + b4.z,
                                              (v.w - mean) * rstd * g4.w + b4.w);
    uint2 u;
    u.x = *(unsigned int*)&p0;
    u.y = *(unsigned int*)&p1;
    *(uint2*)(out + (size_t)row * DIM + tid * 4) = u;
}

// ---------------------------------------------------------------------------
// bf16 tensor-core GEMM: C = epilogue(A[M,K]bf16 @ B[K,N]bf16 + bias)
//   EPI 0: + bias                         (CT = float)
//   EPI 1: res + ls * (acc + bias)        (CT = float)
//   EPI 2: gelu_exact(acc + bias)         (CT = bf16)
// 128x128 block tile, BK=32, 256 threads (8 warps, 2x4), warp tile 64x32.
// mma.sync.m16n8k16 bf16, fp32 accumulate. cp.async double-buffered.
// ---------------------------------------------------------------------------
#define ASTRIDE 40      // elems per A smem row (80B, ldmatrix conflict-free)
#define BSTRIDE 136     // elems per B smem row (272B, conflict-free)
#define ASTAGE  (128 * ASTRIDE)     // elems per A stage
#define BSTAGE  (32  * BSTRIDE)     // elems per B stage

__device__ __forceinline__ float gelu_exact(float x) {
    return 0.5f * x * (1.0f + erff(x * 0.70710678118654752440f));
}

__device__ __forceinline__ void cp16(unsigned int dst, const void* src, int szbytes) {
    asm volatile("cp.async.cg.shared.global [%0], [%1], 16, %2;\n"
                 :: "r"(dst), "l"(src), "r"(szbytes));
}

template<int EPI, typename CT>
__global__ void __launch_bounds__(256) bgemm_kernel(
    const __nv_bfloat16* __restrict__ A, const __nv_bfloat16* __restrict__ B,
    const float* __restrict__ bias, const float* __restrict__ res,
    const float* __restrict__ ls, CT* __restrict__ C,
    int M, int N, int K)
{
    __shared__ __nv_bfloat16 As[2 * ASTAGE];
    __shared__ __nv_bfloat16 Bs[2 * BSTAGE];

    const int tid  = threadIdx.x;
    const int lane = tid & 31;
    const int warp = tid >> 5;
    const int wm   = warp >> 2;          // 0..1
    const int wn   = warp & 3;           // 0..3
    const int rowBase = blockIdx.y * 128;
    const int colBase = blockIdx.x * 128;

    const unsigned int sA = (unsigned int)__cvta_generic_to_shared(As);
    const unsigned int sB = (unsigned int)__cvta_generic_to_shared(Bs);

    // global->smem load assignments
    const int ar = tid >> 2;             // A row 0..63 (+64)
    const int ac = (tid & 3) * 8;        // A col elem
    const int br = tid >> 4;             // B row 0..15 (+16)
    const int bc = (tid & 15) * 8;       // B col elem

    // ldmatrix lane geometry
    const int lg = lane >> 3;            // group 0..3
    const int lr = lane & 7;
    const int a_row = (lg & 1) * 8 + lr; // within 16x16 tile
    const int a_col = (lg >> 1) * 8;
    // for B trans: row within k16 = (lg&1)*8+lr ; col offset (lg>>1)*8

    float acc[4][4][4];
    #pragma unroll
    for (int i = 0; i < 4; i++)
        #pragma unroll
        for (int j = 0; j < 4; j++)
            #pragma unroll
            for (int r = 0; r < 4; r++) acc[i][j][r] = 0.f;

    const int nIter = K >> 5;            // K/32

    // ---- tile loader ----
    auto loadTile = [&](int it, int buf) {
        const int k0 = it << 5;
        #pragma unroll
        for (int i = 0; i < 2; i++) {
            int r  = ar + i * 64;
            int gr = rowBase + r;
            int ok = (gr < M) ? 16 : 0;
            int grc = (gr < M) ? gr : (M - 1);
            cp16(sA + (buf * ASTAGE + r * ASTRIDE + ac) * 2,
                 A + (size_t)grc * K + k0 + ac, ok);
        }
        #pragma unroll
        for (int i = 0; i < 2; i++) {
            int r = br + i * 16;
            cp16(sB + (buf * BSTAGE + r * BSTRIDE + bc) * 2,
                 B + (size_t)(k0 + r) * N + colBase + bc, 16);
        }
        asm volatile("cp.async.commit_group;\n" ::: "memory");
    };

    loadTile(0, 0);
    int buf = 0;

    for (int it = 0; it < nIter; it++) {
        if (it + 1 < nIter) {
            loadTile(it + 1, buf ^ 1);
            asm volatile("cp.async.wait_group 1;\n" ::: "memory");
        } else {
            asm volatile("cp.async.wait_group 0;\n" ::: "memory");
        }
        __syncthreads();

        const unsigned int aBase = sA + buf * ASTAGE * 2;
        const unsigned int bBase = sB + buf * BSTAGE * 2;

        #pragma unroll
        for (int kk = 0; kk < 2; kk++) {
            unsigned int a[4][4];
            #pragma unroll
            for (int i = 0; i < 4; i++) {
                unsigned int addr = aBase +
                    ((wm * 64 + i * 16 + a_row) * ASTRIDE + kk * 16 + a_col) * 2;
                asm volatile("ldmatrix.sync.aligned.m8n8.x4.shared.b16 {%0,%1,%2,%3}, [%4];"
                             : "=r"(a[i][0]), "=r"(a[i][1]), "=r"(a[i][2]), "=r"(a[i][3])
                             : "r"(addr));
            }
            unsigned int b[4][2];
            #pragma unroll
            for (int j = 0; j < 2; j++) {
                unsigned int addr = bBase +
                    ((kk * 16 + (lg & 1) * 8 + lr) * BSTRIDE +
                     wn * 32 + j * 16 + (lg >> 1) * 8) * 2;
                asm volatile("ldmatrix.sync.aligned.m8n8.x4.trans.shared.b16 {%0,%1,%2,%3}, [%4];"
                             : "=r"(b[2*j][0]), "=r"(b[2*j][1]),
                               "=r"(b[2*j+1][0]), "=r"(b[2*j+1][1])
                             : "r"(addr));
            }
            #pragma unroll
            for (int i = 0; i < 4; i++)
                #pragma unroll
                for (int j = 0; j < 4; j++) {
                    asm volatile(
                        "mma.sync.aligned.m16n8k16.row.col.f32.bf16.bf16.f32 "
                        "{%0,%1,%2,%3},{%4,%5,%6,%7},{%8,%9},{%0,%1,%2,%3};"
                        : "+f"(acc[i][j][0]), "+f"(acc[i][j][1]),
                          "+f"(acc[i][j][2]), "+f"(acc[i][j][3])
                        : "r"(a[i][0]), "r"(a[i][1]), "r"(a[i][2]), "r"(a[i][3]),
                          "r"(b[j][0]), "r"(b[j][1]));
                }
        }
        __syncthreads();
        buf ^= 1;
    }

    // ---- epilogue ----
    const int crow = lane >> 2;
    const int ccol = (lane & 3) * 2;
    #pragma unroll
    for (int i = 0; i < 4; i++) {
        #pragma unroll
        for (int rh = 0; rh < 2; rh++) {
            int gr = rowBase + wm * 64 + i * 16 + crow + rh * 8;
            if (gr >= M) continue;
            #pragma unroll
            for (int j = 0; j < 4; j++) {
                int gc = colBase + wn * 32 + j * 8 + ccol;
                float v0 = acc[i][j][rh * 2 + 0] + __ldg(&bias[gc]);
                float v1 = acc[i][j][rh * 2 + 1] + __ldg(&bias[gc + 1]);
                if (EPI == 1) {
                    const float* rp = res + (size_t)gr * N + gc;
                    v0 = __ldg(rp)     + __ldg(&ls[gc])     * v0;
                    v1 = __ldg(rp + 1) + __ldg(&ls[gc + 1]) * v1;
                } else if (EPI == 2) {
                    v0 = gelu_exact(v0);
                    v1 = gelu_exact(v1);
                }
                CT* cp = C + (size_t)gr * N + gc;
                if (sizeof(CT) == 4) {
                    ((float*)cp)[0] = v0;
                    ((float*)cp)[1] = v1;
                } else {
                    __nv_bfloat162 p = __floats2bfloat162_rn(v0, v1);
                    *(__nv_bfloat162*)cp = p;
                }
            }
        }
    }
}

// ---------------------------------------------------------------------------
// Flash attention (fp32 math), bf16 output.
// One CTA per (q-block of 64, head). QKV row: [q|k|v] each 1024.
// ---------------------------------------------------------------------------
#define QB0 22
#define QB1 5
#define NQB (B0 * QB0 + B1 * QB1)    // 128

#define AT_QS   (64 * 68)
#define AT_PS   (64 * 72)
#define ATTN_SMEM_FLOATS (3 * AT_QS + AT_PS + 3 * 64)
#define ATTN_SMEM_BYTES  (ATTN_SMEM_FLOATS * 4)

__global__ void __launch_bounds__(256) attn_kernel(
    const float* __restrict__ QKV, __nv_bfloat16* __restrict__ ATT)
{
    extern __shared__ float sm[];
    float* Qs = sm;
    float* Ks = Qs + AT_QS;
    float* Vs = Ks + AT_QS;
    float* Ps = Vs + AT_QS;
    float* m_s    = Ps + AT_PS;
    float* l_s    = m_s + 64;
    float* corr_s = l_s + 64;

    const int tid = threadIdx.x;
    const int h   = blockIdx.y;
    const int qb  = blockIdx.x;

    int tok0, n, q0;
    if (qb < B0 * QB0) {
        int s = qb / QB0;  q0 = (qb % QB0) * 64;  n = N0;  tok0 = s * N0;
    } else {
        int t = qb - B0 * QB0;
        int s = t / QB1;   q0 = (t % QB1) * 64;   n = N1;  tok0 = T0 + s * N1;
    }

    const int tx = tid & 15;
    const int ty = tid >> 4;

    if (tid < 64) { m_s[tid] = -1e30f; l_s[tid] = 0.f; }

    {
        int q  = tid >> 2;
        int d0 = (tid & 3) * 16;
        int gq = q0 + q;
        const float* src = QKV + (size_t)(tok0 + ((gq < n) ? gq : 0)) * (3 * DIM) + h * DH + d0;
        bool valid = (gq < n);
        #pragma unroll
        for (int j = 0; j < 16; j++)
            Qs[(d0 + j) * 68 + q] = valid ? src[j] * 0.125f : 0.f;
    }
    __syncthreads();

    float acc_o[4][4] = {};

    const int nkt = (n + 63) >> 6;
    for (int kt = 0; kt < nkt; kt++) {
        const int kbase = kt << 6;

        {
            int k  = tid >> 2;
            int d0 = (tid & 3) * 16;
            int gk = kbase + k;
            bool valid = (gk < n);
            const float* kp = QKV + (size_t)(tok0 + (valid ? gk : 0)) * (3 * DIM) + DIM     + h * DH + d0;
            const float* vp = QKV + (size_t)(tok0 + (valid ? gk : 0)) * (3 * DIM) + 2 * DIM + h * DH + d0;
            if (valid) {
                #pragma unroll
                for (int j = 0; j < 16; j += 4) {
                    float4 kv = *(const float4*)(kp + j);
                    Ks[(d0 + j + 0) * 68 + k] = kv.x;
                    Ks[(d0 + j + 1) * 68 + k] = kv.y;
                    Ks[(d0 + j + 2) * 68 + k] = kv.z;
                    Ks[(d0 + j + 3) * 68 + k] = kv.w;
                    *(float4*)(Vs + k * 68 + d0 + j) = *(const float4*)(vp + j);
                }
            } else {
                #pragma unroll
                for (int j = 0; j < 16; j++) Ks[(d0 + j) * 68 + k] = 0.f;
                #pragma unroll
                for (int j = 0; j < 16; j += 4)
                    *(float4*)(Vs + k * 68 + d0 + j) = make_float4(0.f, 0.f, 0.f, 0.f);
            }
        }
        __syncthreads();

        float acc_s[4][4] = {};
        #pragma unroll 4
        for (int d = 0; d < 64; d++) {
            float4 a4 = *(const float4*)(Qs + d * 68 + ty * 4);
            float4 b4 = *(const float4*)(Ks + d * 68 + tx * 4);
            float a[4] = {a4.x, a4.y, a4.z, a4.w};
            float b[4] = {b4.x, b4.y, b4.z, b4.w};
            #pragma unroll
            for (int i = 0; i < 4; i++)
                #pragma unroll
                for (int j = 0; j < 4; j++)
                    acc_s[i][j] += a[i] * b[j];
        }
        #pragma unroll
        for (int i = 0; i < 4; i++)
            *(float4*)(Ps + (ty * 4 + i) * 72 + tx * 4) =
                make_float4(acc_s[i][0], acc_s[i][1], acc_s[i][2], acc_s[i][3]);
        __syncthreads();

        {
            int row = tid >> 2, sub = tid & 3;
            float vals[16];
            float mx = -1e30f;
            #pragma unroll
            for (int j = 0; j < 16; j++) {
                int k = sub * 16 + j;
                float sv = Ps[row * 72 + k];
                if (kbase + k >= n) sv = -1e30f;
                vals[j] = sv;
                mx = fmaxf(mx, sv);
            }
            mx = fmaxf(mx, __shfl_xor_sync(0xffffffffu, mx, 1));
            mx = fmaxf(mx, __shfl_xor_sync(0xffffffffu, mx, 2));
            float m_old = m_s[row];
            float m_new = fmaxf(m_old, mx);
            float ssum = 0.f;
            #pragma unroll
            for (int j = 0; j < 16; j++) {
                float p = expf(vals[j] - m_new);
                Ps[row * 72 + sub * 16 + j] = p;
                ssum += p;
            }
            ssum += __shfl_xor_sync(0xffffffffu, ssum, 1);
            ssum += __shfl_xor_sync(0xffffffffu, ssum, 2);
            if (sub == 0) {
                float corr = expf(m_old - m_new);
                corr_s[row] = corr;
                m_s[row]    = m_new;
                l_s[row]    = l_s[row] * corr + ssum;
            }
        }
        __syncthreads();

        #pragma unroll
        for (int i = 0; i < 4; i++) {
            float c = corr_s[ty * 4 + i];
            #pragma unroll
            for (int j = 0; j < 4; j++) acc_o[i][j] *= c;
        }
        #pragma unroll 4
        for (int k = 0; k < 64; k++) {
            float4 b4 = *(const float4*)(Vs + k * 68 + tx * 4);
            float b[4] = {b4.x, b4.y, b4.z, b4.w};
            float a[4];
            #pragma unroll
            for (int i = 0; i < 4; i++) a[i] = Ps[(ty * 4 + i) * 72 + k];
            #pragma unroll
            for (int i = 0; i < 4; i++)
                #pragma unroll
                for (int j = 0; j < 4; j++)
                    acc_o[i][j] += a[i] * b[j];
        }
        __syncthreads();
    }

    #pragma unroll
    for (int i = 0; i < 4; i++) {
        int gq = q0 + ty * 4 + i;
        if (gq < n) {
            float inv = 1.0f / l_s[ty * 4 + i];
            __nv_bfloat162 p0 = __floats2bfloat162_rn(acc_o[i][0] * inv, acc_o[i][1] * inv);
            __nv_bfloat162 p1 = __floats2bfloat162_rn(acc_o[i][2] * inv, acc_o[i][3] * inv);
            uint2 u;
            u.x = *(unsigned int*)&p0;
            u.y = *(unsigned int*)&p1;
            *(uint2*)(ATT + (size_t)(tok0 + gq) * DIM + h * DH + tx * 4) = u;
        }
    }
}

// ---------------------------------------------------------------------------
// Launch
// ---------------------------------------------------------------------------
extern "C" void kernel_launch(void* const* d_in, const int* in_sizes, int n_in,
                              void* d_out, int out_size)
{
    const float* x0     = (const float*)d_in[0];
    const float* x1     = (const float*)d_in[1];
    const float* ln1_g  = (const float*)d_in[2];
    const float* ln1_b  = (const float*)d_in[3];
    const float* qkv_w  = (const float*)d_in[4];
    const float* qkv_b  = (const float*)d_in[5];
    const float* proj_w = (const float*)d_in[6];
    const float* proj_b = (const float*)d_in[7];
    const float* ls1    = (const float*)d_in[8];
    const float* ln2_g  = (const float*)d_in[9];
    const float* ln2_b  = (const float*)d_in[10];
    const float* fc1_w  = (const float*)d_in[11];
    const float* fc1_b  = (const float*)d_in[12];
    const float* fc2_w  = (const float*)d_in[13];
    const float* fc2_b  = (const float*)d_in[14];
    const float* ls2    = (const float*)d_in[15];

    void *pX, *pQKV, *pH, *pYb, *pATTb, *pGb, *pWb;
    cudaGetSymbolAddress(&pX,    g_X);
    cudaGetSymbolAddress(&pQKV,  g_QKV);
    cudaGetSymbolAddress(&pH,    g_H);
    cudaGetSymbolAddress(&pYb,   g_Yb);
    cudaGetSymbolAddress(&pATTb, g_ATTb);
    cudaGetSymbolAddress(&pGb,   g_Gb);
    cudaGetSymbolAddress(&pWb,   g_Wb);
    float* X   = (float*)pX;
    float* QKV = (float*)pQKV;
    float* H   = (float*)pH;
    __nv_bfloat16* Yb   = (__nv_bfloat16*)pYb;
    __nv_bfloat16* ATTb = (__nv_bfloat16*)pATTb;
    __nv_bfloat16* Gb   = (__nv_bfloat16*)pGb;
    __nv_bfloat16* Wb   = (__nv_bfloat16*)pWb;
    float* OUT = (float*)d_out;

    const int mTiles = (TT + 127) / 128;   // 59

    // 0. weight conversion fp32 -> bf16
    {
        int n;
        n = DIM * 3 * DIM / 4; f2b_kernel<<<(n + 255) / 256, 256>>>(qkv_w,  Wb + WOFF_QKV,  n);
        n = DIM * DIM / 4;     f2b_kernel<<<(n + 255) / 256, 256>>>(proj_w, Wb + WOFF_PROJ, n);
        n = DIM * HID / 4;     f2b_kernel<<<(n + 255) / 256, 256>>>(fc1_w,  Wb + WOFF_FC1,  n);
        n = HID * DIM / 4;     f2b_kernel<<<(n + 255) / 256, 256>>>(fc2_w,  Wb + WOFF_FC2,  n);
    }

    // 1. pack x0 | x1 -> X
    {
        int n4a = T0 * DIM / 4, n4b = T1 * DIM / 4;
        copy4_kernel<<<(n4a + 255) / 256, 256>>>(x0, X, n4a);
        copy4_kernel<<<(n4b + 255) / 256, 256>>>(x1, X + (size_t)T0 * DIM, n4b);
    }

    // 2. LN1: Yb = LN(X)
    ln_kernel<<<TT, 256>>>(X, ln1_g, ln1_b, Yb);

    // 3. QKV = Yb @ qkv_w + qkv_b   (fp32 out)
    bgemm_kernel<0, float><<<dim3(3 * DIM / 128, mTiles), 256>>>(
        Yb, Wb + WOFF_QKV, qkv_b, nullptr, nullptr, QKV, TT, 3 * DIM, DIM);

    // 4. attention -> ATTb (bf16)
    cudaFuncSetAttribute(attn_kernel, cudaFuncAttributeMaxDynamicSharedMemorySize,
                         ATTN_SMEM_BYTES);
    attn_kernel<<<dim3(NQB, NH), 256, ATTN_SMEM_BYTES>>>(QKV, ATTb);

    // 5. H = X + ls1 * (ATTb @ proj_w + proj_b)
    bgemm_kernel<1, float><<<dim3(DIM / 128, mTiles), 256>>>(
        ATTb, Wb + WOFF_PROJ, proj_b, X, ls1, H, TT, DIM, DIM);

    // 6. LN2: Yb = LN(H)
    ln_kernel<<<TT, 256>>>(H, ln2_g, ln2_b, Yb);

    // 7. Gb = gelu(Yb @ fc1_w + fc1_b)  (bf16 out)
    bgemm_kernel<2, __nv_bfloat16><<<dim3(HID / 128, mTiles), 256>>>(
        Yb, Wb + WOFF_FC1, fc1_b, nullptr, nullptr, Gb, TT, HID, DIM);

    // 8. OUT = H + ls2 * (Gb @ fc2_w + fc2_b)
    bgemm_kernel<1, float><<<dim3(DIM / 128, mTiles), 256>>>(
        Gb, Wb + WOFF_FC2, fc2_b, H, ls2, OUT, TT, DIM, HID);
}

// round 5
// speedup vs baseline: 6.2195x; 2.1679x over previous
#include <cuda_runtime.h>
#include <cuda_bf16.h>
#include <math.h>

// ---------------------------------------------------------------------------
// Problem constants
// ---------------------------------------------------------------------------
#define DIM   1024
#define HID   4096
#define NH    16
#define DH    64
#define N0    1370
#define B0    4
#define N1    257
#define B1    8
#define T0    (B0 * N0)          // 5480
#define T1    (B1 * N1)          // 2056
#define TT    (T0 + T1)          // 7536 tokens
#define LN_EPS 1e-5f

// ---------------------------------------------------------------------------
// Scratch
// ---------------------------------------------------------------------------
__device__ float g_X  [(size_t)TT * DIM];            // packed input (fp32)
__device__ float g_H  [(size_t)TT * DIM];            // post-attention residual (fp32)
__device__ __nv_bfloat16 g_QKVb[(size_t)TT * 3 * DIM]; // qkv (bf16)
__device__ __nv_bfloat16 g_Yb  [(size_t)TT * DIM];   // LN output (bf16)
__device__ __nv_bfloat16 g_ATTb[(size_t)TT * DIM];   // attention output (bf16)
__device__ __nv_bfloat16 g_Gb  [(size_t)TT * HID];   // gelu(fc1) (bf16)
#define WOFF_QKV  0
#define WOFF_PROJ ((size_t)DIM * 3 * DIM)
#define WOFF_FC1  (WOFF_PROJ + (size_t)DIM * DIM)
#define WOFF_FC2  (WOFF_FC1 + (size_t)DIM * HID)
#define W_TOTAL   (WOFF_FC2 + (size_t)HID * DIM)
__device__ __nv_bfloat16 g_Wb[W_TOTAL];

// ---------------------------------------------------------------------------
// asm helpers
// ---------------------------------------------------------------------------
__device__ __forceinline__ void cp16(unsigned int dst, const void* src, int szbytes) {
    asm volatile("cp.async.cg.shared.global [%0], [%1], 16, %2;\n"
                 :: "r"(dst), "l"(src), "r"(szbytes));
}
#define LDSM4(r0,r1,r2,r3,addr) \
    asm volatile("ldmatrix.sync.aligned.m8n8.x4.shared.b16 {%0,%1,%2,%3}, [%4];" \
                 : "=r"(r0),"=r"(r1),"=r"(r2),"=r"(r3) : "r"(addr))
#define LDSM4T(r0,r1,r2,r3,addr) \
    asm volatile("ldmatrix.sync.aligned.m8n8.x4.trans.shared.b16 {%0,%1,%2,%3}, [%4];" \
                 : "=r"(r0),"=r"(r1),"=r"(r2),"=r"(r3) : "r"(addr))
#define MMA16816(acc,a0,a1,a2,a3,b0,b1) \
    asm volatile("mma.sync.aligned.m16n8k16.row.col.f32.bf16.bf16.f32 " \
                 "{%0,%1,%2,%3},{%4,%5,%6,%7},{%8,%9},{%0,%1,%2,%3};" \
                 : "+f"(acc[0]),"+f"(acc[1]),"+f"(acc[2]),"+f"(acc[3]) \
                 : "r"(a0),"r"(a1),"r"(a2),"r"(a3),"r"(b0),"r"(b1))

__device__ __forceinline__ unsigned int pack_bf2(float lo, float hi) {
    __nv_bfloat162 t = __floats2bfloat162_rn(lo, hi);
    return *(unsigned int*)&t;
}

// ---------------------------------------------------------------------------
// Elementwise kernels
// ---------------------------------------------------------------------------
__global__ void copy4_kernel(const float* __restrict__ src, float* __restrict__ dst, int n4) {
    int i = blockIdx.x * blockDim.x + threadIdx.x;
    if (i < n4) ((float4*)dst)[i] = ((const float4*)src)[i];
}

__global__ void f2b_kernel(const float* __restrict__ src, __nv_bfloat16* __restrict__ dst, int n4) {
    int i = blockIdx.x * blockDim.x + threadIdx.x;
    if (i < n4) {
        float4 v = ((const float4*)src)[i];
        uint2 u;
        u.x = pack_bf2(v.x, v.y);
        u.y = pack_bf2(v.z, v.w);
        ((uint2*)dst)[i] = u;
    }
}

// ---------------------------------------------------------------------------
// LayerNorm (fp32 in, bf16 out)
// ---------------------------------------------------------------------------
__global__ void __launch_bounds__(256) ln_kernel(
    const float* __restrict__ in, const float* __restrict__ gm,
    const float* __restrict__ bt, __nv_bfloat16* __restrict__ out)
{
    int row = blockIdx.x;
    int tid = threadIdx.x;
    const float4 v = *(const float4*)(in + (size_t)row * DIM + tid * 4);

    float s = v.x + v.y + v.z + v.w;
    float q = v.x * v.x + v.y * v.y + v.z * v.z + v.w * v.w;
    #pragma unroll
    for (int o = 16; o > 0; o >>= 1) {
        s += __shfl_xor_sync(0xffffffffu, s, o);
        q += __shfl_xor_sync(0xffffffffu, q, o);
    }
    __shared__ float ss[8], qq[8];
    if ((tid & 31) == 0) { ss[tid >> 5] = s; qq[tid >> 5] = q; }
    __syncthreads();
    float st = 0.f, qt = 0.f;
    #pragma unroll
    for (int i = 0; i < 8; i++) { st += ss[i]; qt += qq[i]; }

    float mean = st * (1.0f / DIM);
    float var  = qt * (1.0f / DIM) - mean * mean;
    float rstd = rsqrtf(var + LN_EPS);

    float4 g4 = *(const float4*)(gm + tid * 4);
    float4 b4 = *(const float4*)(bt + tid * 4);
    uint2 u;
    u.x = pack_bf2((v.x - mean) * rstd * g4.x + b4.x,
                   (v.y - mean) * rstd * g4.y + b4.y);
    u.y = pack_bf2((v.z - mean) * rstd * g4.z + b4.z,
                   (v.w - mean) * rstd * g4.w + b4.w);
    *(uint2*)(out + (size_t)row * DIM + tid * 4) = u;
}

// ---------------------------------------------------------------------------
// bf16 tensor-core GEMM
// ---------------------------------------------------------------------------
#define ASTRIDE 40
#define BSTRIDE 136
#define ASTAGE  (128 * ASTRIDE)
#define BSTAGE  (32  * BSTRIDE)

__device__ __forceinline__ float gelu_exact(float x) {
    return 0.5f * x * (1.0f + erff(x * 0.70710678118654752440f));
}

template<int EPI, typename CT>
__global__ void __launch_bounds__(256) bgemm_kernel(
    const __nv_bfloat16* __restrict__ A, const __nv_bfloat16* __restrict__ B,
    const float* __restrict__ bias, const float* __restrict__ res,
    const float* __restrict__ ls, CT* __restrict__ C,
    int M, int N, int K)
{
    __shared__ __align__(16) __nv_bfloat16 As[2 * ASTAGE];
    __shared__ __align__(16) __nv_bfloat16 Bs[2 * BSTAGE];

    const int tid  = threadIdx.x;
    const int lane = tid & 31;
    const int warp = tid >> 5;
    const int wm   = warp >> 2;
    const int wn   = warp & 3;
    const int rowBase = blockIdx.y * 128;
    const int colBase = blockIdx.x * 128;

    const unsigned int sA = (unsigned int)__cvta_generic_to_shared(As);
    const unsigned int sB = (unsigned int)__cvta_generic_to_shared(Bs);

    const int ar = tid >> 2;
    const int ac = (tid & 3) * 8;
    const int br = tid >> 4;
    const int bc = (tid & 15) * 8;

    const int lg = lane >> 3;
    const int lr = lane & 7;
    const int a_row = (lg & 1) * 8 + lr;
    const int a_col = (lg >> 1) * 8;

    float acc[4][4][4];
    #pragma unroll
    for (int i = 0; i < 4; i++)
        #pragma unroll
        for (int j = 0; j < 4; j++)
            #pragma unroll
            for (int r = 0; r < 4; r++) acc[i][j][r] = 0.f;

    const int nIter = K >> 5;

    auto loadTile = [&](int it, int buf) {
        const int k0 = it << 5;
        #pragma unroll
        for (int i = 0; i < 2; i++) {
            int r  = ar + i * 64;
            int gr = rowBase + r;
            int ok = (gr < M) ? 16 : 0;
            int grc = (gr < M) ? gr : (M - 1);
            cp16(sA + (buf * ASTAGE + r * ASTRIDE + ac) * 2,
                 A + (size_t)grc * K + k0 + ac, ok);
        }
        #pragma unroll
        for (int i = 0; i < 2; i++) {
            int r = br + i * 16;
            cp16(sB + (buf * BSTAGE + r * BSTRIDE + bc) * 2,
                 B + (size_t)(k0 + r) * N + colBase + bc, 16);
        }
        asm volatile("cp.async.commit_group;\n" ::: "memory");
    };

    loadTile(0, 0);
    int buf = 0;

    for (int it = 0; it < nIter; it++) {
        if (it + 1 < nIter) {
            loadTile(it + 1, buf ^ 1);
            asm volatile("cp.async.wait_group 1;\n" ::: "memory");
        } else {
            asm volatile("cp.async.wait_group 0;\n" ::: "memory");
        }
        __syncthreads();

        const unsigned int aBase = sA + buf * ASTAGE * 2;
        const unsigned int bBase = sB + buf * BSTAGE * 2;

        #pragma unroll
        for (int kk = 0; kk < 2; kk++) {
            unsigned int a[4][4];
            #pragma unroll
            for (int i = 0; i < 4; i++) {
                unsigned int addr = aBase +
                    ((wm * 64 + i * 16 + a_row) * ASTRIDE + kk * 16 + a_col) * 2;
                LDSM4(a[i][0], a[i][1], a[i][2], a[i][3], addr);
            }
            unsigned int b[4][2];
            #pragma unroll
            for (int j = 0; j < 2; j++) {
                unsigned int addr = bBase +
                    ((kk * 16 + (lg & 1) * 8 + lr) * BSTRIDE +
                     wn * 32 + j * 16 + (lg >> 1) * 8) * 2;
                LDSM4T(b[2*j][0], b[2*j][1], b[2*j+1][0], b[2*j+1][1], addr);
            }
            #pragma unroll
            for (int i = 0; i < 4; i++)
                #pragma unroll
                for (int j = 0; j < 4; j++)
                    MMA16816(acc[i][j], a[i][0], a[i][1], a[i][2], a[i][3],
                             b[j][0], b[j][1]);
        }
        __syncthreads();
        buf ^= 1;
    }

    const int crow = lane >> 2;
    const int ccol = (lane & 3) * 2;
    #pragma unroll
    for (int i = 0; i < 4; i++) {
        #pragma unroll
        for (int rh = 0; rh < 2; rh++) {
            int gr = rowBase + wm * 64 + i * 16 + crow + rh * 8;
            if (gr >= M) continue;
            #pragma unroll
            for (int j = 0; j < 4; j++) {
                int gc = colBase + wn * 32 + j * 8 + ccol;
                float v0 = acc[i][j][rh * 2 + 0] + __ldg(&bias[gc]);
                float v1 = acc[i][j][rh * 2 + 1] + __ldg(&bias[gc + 1]);
                if (EPI == 1) {
                    const float* rp = res + (size_t)gr * N + gc;
                    v0 = __ldg(rp)     + __ldg(&ls[gc])     * v0;
                    v1 = __ldg(rp + 1) + __ldg(&ls[gc + 1]) * v1;
                } else if (EPI == 2) {
                    v0 = gelu_exact(v0);
                    v1 = gelu_exact(v1);
                }
                CT* cp = C + (size_t)gr * N + gc;
                if (sizeof(CT) == 4) {
                    ((float*)cp)[0] = v0;
                    ((float*)cp)[1] = v1;
                } else {
                    *(unsigned int*)cp = pack_bf2(v0, v1);
                }
            }
        }
    }
}

// ---------------------------------------------------------------------------
// bf16 tensor-core flash attention.
// 128 threads (4 warps). CTA = (64-query block, head). 64-key tiles,
// cp.async double-buffered K/V. Warp owns 16 query rows; softmax fully in
// registers; P (S-accumulator layout) re-packed to bf16 A-fragments in regs.
// QKV row layout: [q(1024) | k(1024) | v(1024)] bf16, head h at h*64.
// ---------------------------------------------------------------------------
#define QB0 22
#define QB1 5
#define NQB (B0 * QB0 + B1 * QB1)    // 128

#define FSTR  72                      // smem row stride (elems): 144B = 9*16B
#define FTSZ  (64 * FSTR)             // one tile

__global__ void __launch_bounds__(128) attn_kernel(
    const __nv_bfloat16* __restrict__ QKV, __nv_bfloat16* __restrict__ ATT)
{
    __shared__ __align__(16) __nv_bfloat16 sQ[FTSZ];
    __shared__ __align__(16) __nv_bfloat16 sK[2][FTSZ];
    __shared__ __align__(16) __nv_bfloat16 sV[2][FTSZ];

    const int tid  = threadIdx.x;
    const int lane = tid & 31;
    const int w    = tid >> 5;
    const int lg   = lane >> 3;
    const int lr   = lane & 7;
    const int h    = blockIdx.y;
    const int qb   = blockIdx.x;

    int tok0, n, q0;
    if (qb < B0 * QB0) {
        int s = qb / QB0;  q0 = (qb % QB0) * 64;  n = N0;  tok0 = s * N0;
    } else {
        int t = qb - B0 * QB0;
        int s = t / QB1;   q0 = (t % QB1) * 64;   n = N1;  tok0 = T0 + s * N1;
    }

    const unsigned int sQa = (unsigned int)__cvta_generic_to_shared(sQ);
    const unsigned int sKa = (unsigned int)__cvta_generic_to_shared(sK);
    const unsigned int sVa = (unsigned int)__cvta_generic_to_shared(sV);

    // ---- load Q tile (group 0, together with first K/V) ----
    #pragma unroll
    for (int i = 0; i < 4; i++) {
        int c = tid + i * 128;
        int r = c >> 3, col = (c & 7) * 8;
        int gq = q0 + r;
        int ok = (gq < n) ? 16 : 0;
        const __nv_bfloat16* src =
            QKV + (size_t)(tok0 + ((gq < n) ? gq : 0)) * (3 * DIM) + h * DH + col;
        cp16(sQa + (r * FSTR + col) * 2, src, ok);
    }

    auto loadKV = [&](int kt, int buf) {
        const int kbase = kt << 6;
        #pragma unroll
        for (int i = 0; i < 4; i++) {
            int c = tid + i * 128;
            int r = c >> 3, col = (c & 7) * 8;
            int gk = kbase + r;
            int ok = (gk < n) ? 16 : 0;
            const __nv_bfloat16* base =
                QKV + (size_t)(tok0 + ((gk < n) ? gk : 0)) * (3 * DIM) + h * DH + col;
            cp16(sKa + (buf * FTSZ + r * FSTR + col) * 2, base + DIM,     ok);
            cp16(sVa + (buf * FTSZ + r * FSTR + col) * 2, base + 2 * DIM, ok);
        }
        asm volatile("cp.async.commit_group;\n" ::: "memory");
    };

    loadKV(0, 0);
    asm volatile("cp.async.commit_group;\n" ::: "memory"); // close group (Q+KV0)

    float o[8][4];
    #pragma unroll
    for (int j = 0; j < 8; j++)
        #pragma unroll
        for (int r = 0; r < 4; r++) o[j][r] = 0.f;
    float m0 = -1e30f, m1 = -1e30f, l0 = 0.f, l1 = 0.f;

    const int c0 = (lane & 3) * 2;
    const int nkt = (n + 63) >> 6;
    int buf = 0;

    for (int kt = 0; kt < nkt; kt++) {
        if (kt + 1 < nkt) {
            loadKV(kt + 1, buf ^ 1);
            asm volatile("cp.async.wait_group 1;\n" ::: "memory");
        } else {
            asm volatile("cp.async.wait_group 0;\n" ::: "memory");
        }
        __syncthreads();

        const int kbase = kt << 6;
        const unsigned int sKb = sKa + buf * FTSZ * 2;
        const unsigned int sVb = sVa + buf * FTSZ * 2;

        // ---- S = Q @ K^T ----
        float sacc[8][4];
        #pragma unroll
        for (int j = 0; j < 8; j++)
            #pragma unroll
            for (int r = 0; r < 4; r++) sacc[j][r] = 0.f;

        #pragma unroll
        for (int kk = 0; kk < 4; kk++) {
            unsigned int a0, a1, a2, a3;
            unsigned int aaddr = sQa +
                ((w * 16 + (lg & 1) * 8 + lr) * FSTR + kk * 16 + (lg >> 1) * 8) * 2;
            LDSM4(a0, a1, a2, a3, aaddr);
            #pragma unroll
            for (int jp = 0; jp < 4; jp++) {
                unsigned int b0, b1, b2, b3;
                unsigned int baddr = sKb +
                    ((jp * 16 + (lg >> 1) * 8 + lr) * FSTR + kk * 16 + (lg & 1) * 8) * 2;
                LDSM4(b0, b1, b2, b3, baddr);
                MMA16816(sacc[2 * jp],     a0, a1, a2, a3, b0, b1);
                MMA16816(sacc[2 * jp + 1], a0, a1, a2, a3, b2, b3);
            }
        }

        // ---- softmax (registers; rows r0 = lane>>2, r1 = r0+8) ----
        const bool edge = (kbase + 64 > n);
        float mx0 = -1e30f, mx1 = -1e30f;
        #pragma unroll
        for (int j = 0; j < 8; j++) {
            float v0 = sacc[j][0] * 0.125f;
            float v1 = sacc[j][1] * 0.125f;
            float v2 = sacc[j][2] * 0.125f;
            float v3 = sacc[j][3] * 0.125f;
            if (edge) {
                int col = kbase + j * 8 + c0;
                if (col     >= n) { v0 = -1e30f; v2 = -1e30f; }
                if (col + 1 >= n) { v1 = -1e30f; v3 = -1e30f; }
            }
            sacc[j][0] = v0; sacc[j][1] = v1; sacc[j][2] = v2; sacc[j][3] = v3;
            mx0 = fmaxf(mx0, fmaxf(v0, v1));
            mx1 = fmaxf(mx1, fmaxf(v2, v3));
        }
        mx0 = fmaxf(mx0, __shfl_xor_sync(0xffffffffu, mx0, 1));
        mx0 = fmaxf(mx0, __shfl_xor_sync(0xffffffffu, mx0, 2));
        mx1 = fmaxf(mx1, __shfl_xor_sync(0xffffffffu, mx1, 1));
        mx1 = fmaxf(mx1, __shfl_xor_sync(0xffffffffu, mx1, 2));

        float mn0 = fmaxf(m0, mx0), mn1 = fmaxf(m1, mx1);
        float corr0 = __expf(m0 - mn0), corr1 = __expf(m1 - mn1);
        m0 = mn0; m1 = mn1;

        float s0 = 0.f, s1 = 0.f;
        #pragma unroll
        for (int j = 0; j < 8; j++) {
            float p0 = __expf(sacc[j][0] - mn0);
            float p1 = __expf(sacc[j][1] - mn0);
            float p2 = __expf(sacc[j][2] - mn1);
            float p3 = __expf(sacc[j][3] - mn1);
            sacc[j][0] = p0; sacc[j][1] = p1; sacc[j][2] = p2; sacc[j][3] = p3;
            s0 += p0 + p1;  s1 += p2 + p3;
        }
        s0 += __shfl_xor_sync(0xffffffffu, s0, 1);
        s0 += __shfl_xor_sync(0xffffffffu, s0, 2);
        s1 += __shfl_xor_sync(0xffffffffu, s1, 1);
        s1 += __shfl_xor_sync(0xffffffffu, s1, 2);
        l0 = l0 * corr0 + s0;
        l1 = l1 * corr1 + s1;

        // ---- rescale O, pack P to bf16 A-fragments ----
        unsigned int pa[8], pb[8];
        #pragma unroll
        for (int j = 0; j < 8; j++) {
            o[j][0] *= corr0; o[j][1] *= corr0;
            o[j][2] *= corr1; o[j][3] *= corr1;
            pa[j] = pack_bf2(sacc[j][0], sacc[j][1]);
            pb[j] = pack_bf2(sacc[j][2], sacc[j][3]);
        }

        // ---- O += P @ V ----
        #pragma unroll
        for (int t = 0; t < 4; t++) {
            #pragma unroll
            for (int jdp = 0; jdp < 4; jdp++) {
                unsigned int v0, v1, v2, v3;
                unsigned int vaddr = sVb +
                    ((t * 16 + (lg & 1) * 8 + lr) * FSTR + jdp * 16 + (lg >> 1) * 8) * 2;
                LDSM4T(v0, v1, v2, v3, vaddr);
                MMA16816(o[2 * jdp],     pa[2*t], pb[2*t], pa[2*t+1], pb[2*t+1], v0, v1);
                MMA16816(o[2 * jdp + 1], pa[2*t], pb[2*t], pa[2*t+1], pb[2*t+1], v2, v3);
            }
        }
        __syncthreads();   // all warps done reading buf before it is refilled
        buf ^= 1;
    }

    // ---- finalize: divide by l, write bf16 ----
    float inv0 = 1.0f / l0, inv1 = 1.0f / l1;
    int r0 = w * 16 + (lane >> 2);
    int gq0 = q0 + r0, gq1 = gq0 + 8;
    #pragma unroll
    for (int jd = 0; jd < 8; jd++) {
        int col = h * DH + jd * 8 + c0;
        if (gq0 < n)
            *(unsigned int*)(ATT + (size_t)(tok0 + gq0) * DIM + col) =
                pack_bf2(o[jd][0] * inv0, o[jd][1] * inv0);
        if (gq1 < n)
            *(unsigned int*)(ATT + (size_t)(tok0 + gq1) * DIM + col) =
                pack_bf2(o[jd][2] * inv1, o[jd][3] * inv1);
    }
}

// ---------------------------------------------------------------------------
// Launch
// ---------------------------------------------------------------------------
extern "C" void kernel_launch(void* const* d_in, const int* in_sizes, int n_in,
                              void* d_out, int out_size)
{
    const float* x0     = (const float*)d_in[0];
    const float* x1     = (const float*)d_in[1];
    const float* ln1_g  = (const float*)d_in[2];
    const float* ln1_b  = (const float*)d_in[3];
    const float* qkv_w  = (const float*)d_in[4];
    const float* qkv_b  = (const float*)d_in[5];
    const float* proj_w = (const float*)d_in[6];
    const float* proj_b = (const float*)d_in[7];
    const float* ls1    = (const float*)d_in[8];
    const float* ln2_g  = (const float*)d_in[9];
    const float* ln2_b  = (const float*)d_in[10];
    const float* fc1_w  = (const float*)d_in[11];
    const float* fc1_b  = (const float*)d_in[12];
    const float* fc2_w  = (const float*)d_in[13];
    const float* fc2_b  = (const float*)d_in[14];
    const float* ls2    = (const float*)d_in[15];

    void *pX, *pH, *pQKVb, *pYb, *pATTb, *pGb, *pWb;
    cudaGetSymbolAddress(&pX,    g_X);
    cudaGetSymbolAddress(&pH,    g_H);
    cudaGetSymbolAddress(&pQKVb, g_QKVb);
    cudaGetSymbolAddress(&pYb,   g_Yb);
    cudaGetSymbolAddress(&pATTb, g_ATTb);
    cudaGetSymbolAddress(&pGb,   g_Gb);
    cudaGetSymbolAddress(&pWb,   g_Wb);
    float* X   = (float*)pX;
    float* H   = (float*)pH;
    __nv_bfloat16* QKVb = (__nv_bfloat16*)pQKVb;
    __nv_bfloat16* Yb   = (__nv_bfloat16*)pYb;
    __nv_bfloat16* ATTb = (__nv_bfloat16*)pATTb;
    __nv_bfloat16* Gb   = (__nv_bfloat16*)pGb;
    __nv_bfloat16* Wb   = (__nv_bfloat16*)pWb;
    float* OUT = (float*)d_out;

    const int mTiles = (TT + 127) / 128;   // 59

    // 0. weight conversion fp32 -> bf16
    {
        int n;
        n = DIM * 3 * DIM / 4; f2b_kernel<<<(n + 255) / 256, 256>>>(qkv_w,  Wb + WOFF_QKV,  n);
        n = DIM * DIM / 4;     f2b_kernel<<<(n + 255) / 256, 256>>>(proj_w, Wb + WOFF_PROJ, n);
        n = DIM * HID / 4;     f2b_kernel<<<(n + 255) / 256, 256>>>(fc1_w,  Wb + WOFF_FC1,  n);
        n = HID * DIM / 4;     f2b_kernel<<<(n + 255) / 256, 256>>>(fc2_w,  Wb + WOFF_FC2,  n);
    }

    // 1. pack x0 | x1 -> X
    {
        int n4a = T0 * DIM / 4, n4b = T1 * DIM / 4;
        copy4_kernel<<<(n4a + 255) / 256, 256>>>(x0, X, n4a);
        copy4_kernel<<<(n4b + 255) / 256, 256>>>(x1, X + (size_t)T0 * DIM, n4b);
    }

    // 2. LN1
    ln_kernel<<<TT, 256>>>(X, ln1_g, ln1_b, Yb);

    // 3. QKV (bf16 out)
    bgemm_kernel<0, __nv_bfloat16><<<dim3(3 * DIM / 128, mTiles), 256>>>(
        Yb, Wb + WOFF_QKV, qkv_b, nullptr, nullptr, QKVb, TT, 3 * DIM, DIM);

    // 4. attention
    attn_kernel<<<dim3(NQB, NH), 128>>>(QKVb, ATTb);

    // 5. H = X + ls1 * (ATT @ proj_w + proj_b)
    bgemm_kernel<1, float><<<dim3(DIM / 128, mTiles), 256>>>(
        ATTb, Wb + WOFF_PROJ, proj_b, X, ls1, H, TT, DIM, DIM);

    // 6. LN2
    ln_kernel<<<TT, 256>>>(H, ln2_g, ln2_b, Yb);

    // 7. Gb = gelu(Yb @ fc1_w + fc1_b)
    bgemm_kernel<2, __nv_bfloat16><<<dim3(HID / 128, mTiles), 256>>>(
        Yb, Wb + WOFF_FC1, fc1_b, nullptr, nullptr, Gb, TT, HID, DIM);

    // 8. OUT = H + ls2 * (Gb @ fc2_w + fc2_b)
    bgemm_kernel<1, float><<<dim3(DIM / 128, mTiles), 256>>>(
        Gb, Wb + WOFF_FC2, fc2_b, H, ls2, OUT, TT, DIM, HID);
}

// round 11
// speedup vs baseline: 6.9452x; 1.1167x over previous
#include <cuda_runtime.h>
#include <cuda_bf16.h>
#include <math.h>

// ---------------------------------------------------------------------------
// Problem constants
// ---------------------------------------------------------------------------
#define DIM   1024
#define HID   4096
#define NH    16
#define DH    64
#define N0    1370
#define B0    4
#define N1    257
#define B1    8
#define T0    (B0 * N0)          // 5480
#define T1    (B1 * N1)          // 2056
#define TT    (T0 + T1)          // 7536 tokens
#define LN_EPS 1e-5f

// ---------------------------------------------------------------------------
// Scratch
// ---------------------------------------------------------------------------
__device__ float g_X  [(size_t)TT * DIM];            // packed input (fp32)
__device__ float g_H  [(size_t)TT * DIM];            // post-attention residual (fp32)
__device__ __nv_bfloat16 g_QKVb[(size_t)TT * 3 * DIM]; // qkv (bf16)
__device__ __nv_bfloat16 g_Yb  [(size_t)TT * DIM];   // LN output (bf16)
__device__ __nv_bfloat16 g_ATTb[(size_t)TT * DIM];   // attention output (bf16)
__device__ __nv_bfloat16 g_Gb  [(size_t)TT * HID];   // gelu(fc1) (bf16)
#define WOFF_QKV  0
#define WOFF_PROJ ((size_t)DIM * 3 * DIM)
#define WOFF_FC1  (WOFF_PROJ + (size_t)DIM * DIM)
#define WOFF_FC2  (WOFF_FC1 + (size_t)DIM * HID)
#define W_TOTAL   (WOFF_FC2 + (size_t)HID * DIM)
__device__ __nv_bfloat16 g_Wb[W_TOTAL];

// ---------------------------------------------------------------------------
// asm helpers
// ---------------------------------------------------------------------------
__device__ __forceinline__ void cp16(unsigned int dst, const void* src, int szbytes) {
    asm volatile("cp.async.cg.shared.global [%0], [%1], 16, %2;\n"
                 :: "r"(dst), "l"(src), "r"(szbytes));
}
#define LDSM4(r0,r1,r2,r3,addr) \
    asm volatile("ldmatrix.sync.aligned.m8n8.x4.shared.b16 {%0,%1,%2,%3}, [%4];" \
                 : "=r"(r0),"=r"(r1),"=r"(r2),"=r"(r3) : "r"(addr))
#define LDSM4T(r0,r1,r2,r3,addr) \
    asm volatile("ldmatrix.sync.aligned.m8n8.x4.trans.shared.b16 {%0,%1,%2,%3}, [%4];" \
                 : "=r"(r0),"=r"(r1),"=r"(r2),"=r"(r3) : "r"(addr))
#define MMA16816(acc,a0,a1,a2,a3,b0,b1) \
    asm volatile("mma.sync.aligned.m16n8k16.row.col.f32.bf16.bf16.f32 " \
                 "{%0,%1,%2,%3},{%4,%5,%6,%7},{%8,%9},{%0,%1,%2,%3};" \
                 : "+f"(acc[0]),"+f"(acc[1]),"+f"(acc[2]),"+f"(acc[3]) \
                 : "r"(a0),"r"(a1),"r"(a2),"r"(a3),"r"(b0),"r"(b1))

__device__ __forceinline__ unsigned int pack_bf2(float lo, float hi) {
    __nv_bfloat162 t = __floats2bfloat162_rn(lo, hi);
    return *(unsigned int*)&t;
}

// ---------------------------------------------------------------------------
// Elementwise kernels
// ---------------------------------------------------------------------------
__global__ void copy4_kernel(const float* __restrict__ src, float* __restrict__ dst, int n4) {
    int i = blockIdx.x * blockDim.x + threadIdx.x;
    if (i < n4) ((float4*)dst)[i] = ((const float4*)src)[i];
}

__global__ void f2b_kernel(const float* __restrict__ src, __nv_bfloat16* __restrict__ dst, int n4) {
    int i = blockIdx.x * blockDim.x + threadIdx.x;
    if (i < n4) {
        float4 v = ((const float4*)src)[i];
        uint2 u;
        u.x = pack_bf2(v.x, v.y);
        u.y = pack_bf2(v.z, v.w);
        ((uint2*)dst)[i] = u;
    }
}

// ---------------------------------------------------------------------------
// LayerNorm (fp32 in, bf16 out)
// ---------------------------------------------------------------------------
__global__ void __launch_bounds__(256) ln_kernel(
    const float* __restrict__ in, const float* __restrict__ gm,
    const float* __restrict__ bt, __nv_bfloat16* __restrict__ out)
{
    int row = blockIdx.x;
    int tid = threadIdx.x;
    const float4 v = *(const float4*)(in + (size_t)row * DIM + tid * 4);

    float s = v.x + v.y + v.z + v.w;
    float q = v.x * v.x + v.y * v.y + v.z * v.z + v.w * v.w;
    #pragma unroll
    for (int o = 16; o > 0; o >>= 1) {
        s += __shfl_xor_sync(0xffffffffu, s, o);
        q += __shfl_xor_sync(0xffffffffu, q, o);
    }
    __shared__ float ss[8], qq[8];
    if ((tid & 31) == 0) { ss[tid >> 5] = s; qq[tid >> 5] = q; }
    __syncthreads();
    float st = 0.f, qt = 0.f;
    #pragma unroll
    for (int i = 0; i < 8; i++) { st += ss[i]; qt += qq[i]; }

    float mean = st * (1.0f / DIM);
    float var  = qt * (1.0f / DIM) - mean * mean;
    float rstd = rsqrtf(var + LN_EPS);

    float4 g4 = *(const float4*)(gm + tid * 4);
    float4 b4 = *(const float4*)(bt + tid * 4);
    uint2 u;
    u.x = pack_bf2((v.x - mean) * rstd * g4.x + b4.x,
                   (v.y - mean) * rstd * g4.y + b4.y);
    u.y = pack_bf2((v.z - mean) * rstd * g4.z + b4.z,
                   (v.w - mean) * rstd * g4.w + b4.w);
    *(uint2*)(out + (size_t)row * DIM + tid * 4) = u;
}

// ---------------------------------------------------------------------------
// bf16 tensor-core GEMM, v2:
// block 128x128, 4 warps (2x2), warp tile 64x64, BK=32, 4-stage cp.async
// pipeline with ONE __syncthreads per K-slice.
// ---------------------------------------------------------------------------
#define ASTRIDE 40
#define BSTRIDE 136
#define ASTG    (128 * ASTRIDE)     // elems per A stage (5120)
#define BSTG    (32  * BSTRIDE)     // elems per B stage (4352)
#define NSTAGE  4
#define GEMM_SMEM_BYTES ((NSTAGE * (ASTG + BSTG)) * 2)   // 75776 B

__device__ __forceinline__ float gelu_exact(float x) {
    return 0.5f * x * (1.0f + erff(x * 0.70710678118654752440f));
}

template<int EPI, typename CT>
__global__ void __launch_bounds__(128) bgemm_kernel(
    const __nv_bfloat16* __restrict__ A, const __nv_bfloat16* __restrict__ B,
    const float* __restrict__ bias, const float* __restrict__ res,
    const float* __restrict__ ls, CT* __restrict__ C,
    int M, int N, int K)
{
    extern __shared__ __align__(16) __nv_bfloat16 smem[];
    const unsigned int sA = (unsigned int)__cvta_generic_to_shared(smem);
    const unsigned int sB = sA + NSTAGE * ASTG * 2;

    const int tid  = threadIdx.x;
    const int lane = tid & 31;
    const int warp = tid >> 5;
    const int wm   = warp >> 1;          // 0..1
    const int wn   = warp & 1;           // 0..1
    const int rowBase = blockIdx.y * 128;
    const int colBase = blockIdx.x * 128;

    const int lg = lane >> 3;
    const int lr = lane & 7;
    const int a_row = (lg & 1) * 8 + lr;
    const int a_col = (lg >> 1) * 8;

    float acc[4][8][4];
    #pragma unroll
    for (int i = 0; i < 4; i++)
        #pragma unroll
        for (int j = 0; j < 8; j++)
            #pragma unroll
            for (int r = 0; r < 4; r++) acc[i][j][r] = 0.f;

    const int nIter = K >> 5;

    auto loadTile = [&](int it, int s) {
        const int k0 = it << 5;
        #pragma unroll
        for (int i = 0; i < 4; i++) {           // A: 128 rows x 4 chunks
            int task = tid + i * 128;
            int r = task >> 2, c = (task & 3) * 8;
            int gr = rowBase + r;
            int ok = (gr < M) ? 16 : 0;
            int grc = (gr < M) ? gr : (M - 1);
            cp16(sA + (s * ASTG + r * ASTRIDE + c) * 2,
                 A + (size_t)grc * K + k0 + c, ok);
        }
        #pragma unroll
        for (int i = 0; i < 4; i++) {           // B: 32 rows x 16 chunks
            int task = tid + i * 128;
            int r = task >> 4, c = (task & 15) * 8;
            cp16(sB + (s * BSTG + r * BSTRIDE + c) * 2,
                 B + (size_t)(k0 + r) * N + colBase + c, 16);
        }
        asm volatile("cp.async.commit_group;\n" ::: "memory");
    };

    // prologue: stages 0..2
    loadTile(0, 0);
    if (nIter > 1) loadTile(1, 1);
    if (nIter > 2) loadTile(2, 2);

    for (int it = 0; it < nIter; it++) {
        // stage 'it' must be complete; pending beyond it = min(2, nIter-1-it)
        if (it + 2 < nIter)      { asm volatile("cp.async.wait_group 2;\n" ::: "memory"); }
        else if (it + 1 < nIter) { asm volatile("cp.async.wait_group 1;\n" ::: "memory"); }
        else                     { asm volatile("cp.async.wait_group 0;\n" ::: "memory"); }
        __syncthreads();

        if (it + 3 < nIter) loadTile(it + 3, (it + 3) & 3);

        const int s = it & 3;
        const unsigned int aBase = sA + s * ASTG * 2;
        const unsigned int bBase = sB + s * BSTG * 2;

        #pragma unroll
        for (int kk = 0; kk < 2; kk++) {
            unsigned int a[4][4];
            #pragma unroll
            for (int i = 0; i < 4; i++) {
                unsigned int addr = aBase +
                    ((wm * 64 + i * 16 + a_row) * ASTRIDE + kk * 16 + a_col) * 2;
                LDSM4(a[i][0], a[i][1], a[i][2], a[i][3], addr);
            }
            unsigned int b[8][2];
            #pragma unroll
            for (int j = 0; j < 4; j++) {
                unsigned int addr = bBase +
                    ((kk * 16 + (lg & 1) * 8 + lr) * BSTRIDE +
                     wn * 64 + j * 16 + (lg >> 1) * 8) * 2;
                LDSM4T(b[2*j][0], b[2*j][1], b[2*j+1][0], b[2*j+1][1], addr);
            }
            #pragma unroll
            for (int i = 0; i < 4; i++)
                #pragma unroll
                for (int j = 0; j < 8; j++)
                    MMA16816(acc[i][j], a[i][0], a[i][1], a[i][2], a[i][3],
                             b[j][0], b[j][1]);
        }
    }

    // ---- epilogue ----
    const int crow = lane >> 2;
    const int ccol = (lane & 3) * 2;
    #pragma unroll
    for (int i = 0; i < 4; i++) {
        #pragma unroll
        for (int rh = 0; rh < 2; rh++) {
            int gr = rowBase + wm * 64 + i * 16 + crow + rh * 8;
            if (gr >= M) continue;
            #pragma unroll
            for (int j = 0; j < 8; j++) {
                int gc = colBase + wn * 64 + j * 8 + ccol;
                float v0 = acc[i][j][rh * 2 + 0] + __ldg(&bias[gc]);
                float v1 = acc[i][j][rh * 2 + 1] + __ldg(&bias[gc + 1]);
                if (EPI == 1) {
                    const float* rp = res + (size_t)gr * N + gc;
                    v0 = __ldg(rp)     + __ldg(&ls[gc])     * v0;
                    v1 = __ldg(rp + 1) + __ldg(&ls[gc + 1]) * v1;
                } else if (EPI == 2) {
                    v0 = gelu_exact(v0);
                    v1 = gelu_exact(v1);
                }
                CT* cp = C + (size_t)gr * N + gc;
                if (sizeof(CT) == 4) {
                    ((float*)cp)[0] = v0;
                    ((float*)cp)[1] = v1;
                } else {
                    *(unsigned int*)cp = pack_bf2(v0, v1);
                }
            }
        }
    }
}

// ---------------------------------------------------------------------------
// bf16 tensor-core flash attention (unchanged from round 5)
// ---------------------------------------------------------------------------
#define QB0 22
#define QB1 5
#define NQB (B0 * QB0 + B1 * QB1)    // 128

#define FSTR  72
#define FTSZ  (64 * FSTR)

__global__ void __launch_bounds__(128) attn_kernel(
    const __nv_bfloat16* __restrict__ QKV, __nv_bfloat16* __restrict__ ATT)
{
    __shared__ __align__(16) __nv_bfloat16 sQ[FTSZ];
    __shared__ __align__(16) __nv_bfloat16 sK[2][FTSZ];
    __shared__ __align__(16) __nv_bfloat16 sV[2][FTSZ];

    const int tid  = threadIdx.x;
    const int lane = tid & 31;
    const int w    = tid >> 5;
    const int lg   = lane >> 3;
    const int lr   = lane & 7;
    const int h    = blockIdx.y;
    const int qb   = blockIdx.x;

    int tok0, n, q0;
    if (qb < B0 * QB0) {
        int s = qb / QB0;  q0 = (qb % QB0) * 64;  n = N0;  tok0 = s * N0;
    } else {
        int t = qb - B0 * QB0;
        int s = t / QB1;   q0 = (t % QB1) * 64;   n = N1;  tok0 = T0 + s * N1;
    }

    const unsigned int sQa = (unsigned int)__cvta_generic_to_shared(sQ);
    const unsigned int sKa = (unsigned int)__cvta_generic_to_shared(sK);
    const unsigned int sVa = (unsigned int)__cvta_generic_to_shared(sV);

    #pragma unroll
    for (int i = 0; i < 4; i++) {
        int c = tid + i * 128;
        int r = c >> 3, col = (c & 7) * 8;
        int gq = q0 + r;
        int ok = (gq < n) ? 16 : 0;
        const __nv_bfloat16* src =
            QKV + (size_t)(tok0 + ((gq < n) ? gq : 0)) * (3 * DIM) + h * DH + col;
        cp16(sQa + (r * FSTR + col) * 2, src, ok);
    }

    auto loadKV = [&](int kt, int buf) {
        const int kbase = kt << 6;
        #pragma unroll
        for (int i = 0; i < 4; i++) {
            int c = tid + i * 128;
            int r = c >> 3, col = (c & 7) * 8;
            int gk = kbase + r;
            int ok = (gk < n) ? 16 : 0;
            const __nv_bfloat16* base =
                QKV + (size_t)(tok0 + ((gk < n) ? gk : 0)) * (3 * DIM) + h * DH + col;
            cp16(sKa + (buf * FTSZ + r * FSTR + col) * 2, base + DIM,     ok);
            cp16(sVa + (buf * FTSZ + r * FSTR + col) * 2, base + 2 * DIM, ok);
        }
        asm volatile("cp.async.commit_group;\n" ::: "memory");
    };

    loadKV(0, 0);
    asm volatile("cp.async.commit_group;\n" ::: "memory");

    float o[8][4];
    #pragma unroll
    for (int j = 0; j < 8; j++)
        #pragma unroll
        for (int r = 0; r < 4; r++) o[j][r] = 0.f;
    float m0 = -1e30f, m1 = -1e30f, l0 = 0.f, l1 = 0.f;

    const int c0 = (lane & 3) * 2;
    const int nkt = (n + 63) >> 6;
    int buf = 0;

    for (int kt = 0; kt < nkt; kt++) {
        if (kt + 1 < nkt) {
            loadKV(kt + 1, buf ^ 1);
            asm volatile("cp.async.wait_group 1;\n" ::: "memory");
        } else {
            asm volatile("cp.async.wait_group 0;\n" ::: "memory");
        }
        __syncthreads();

        const int kbase = kt << 6;
        const unsigned int sKb = sKa + buf * FTSZ * 2;
        const unsigned int sVb = sVa + buf * FTSZ * 2;

        float sacc[8][4];
        #pragma unroll
        for (int j = 0; j < 8; j++)
            #pragma unroll
            for (int r = 0; r < 4; r++) sacc[j][r] = 0.f;

        #pragma unroll
        for (int kk = 0; kk < 4; kk++) {
            unsigned int a0, a1, a2, a3;
            unsigned int aaddr = sQa +
                ((w * 16 + (lg & 1) * 8 + lr) * FSTR + kk * 16 + (lg >> 1) * 8) * 2;
            LDSM4(a0, a1, a2, a3, aaddr);
            #pragma unroll
            for (int jp = 0; jp < 4; jp++) {
                unsigned int b0, b1, b2, b3;
                unsigned int baddr = sKb +
                    ((jp * 16 + (lg >> 1) * 8 + lr) * FSTR + kk * 16 + (lg & 1) * 8) * 2;
                LDSM4(b0, b1, b2, b3, baddr);
                MMA16816(sacc[2 * jp],     a0, a1, a2, a3, b0, b1);
                MMA16816(sacc[2 * jp + 1], a0, a1, a2, a3, b2, b3);
            }
        }

        const bool edge = (kbase + 64 > n);
        float mx0 = -1e30f, mx1 = -1e30f;
        #pragma unroll
        for (int j = 0; j < 8; j++) {
            float v0 = sacc[j][0] * 0.125f;
            float v1 = sacc[j][1] * 0.125f;
            float v2 = sacc[j][2] * 0.125f;
            float v3 = sacc[j][3] * 0.125f;
            if (edge) {
                int col = kbase + j * 8 + c0;
                if (col     >= n) { v0 = -1e30f; v2 = -1e30f; }
                if (col + 1 >= n) { v1 = -1e30f; v3 = -1e30f; }
            }
            sacc[j][0] = v0; sacc[j][1] = v1; sacc[j][2] = v2; sacc[j][3] = v3;
            mx0 = fmaxf(mx0, fmaxf(v0, v1));
            mx1 = fmaxf(mx1, fmaxf(v2, v3));
        }
        mx0 = fmaxf(mx0, __shfl_xor_sync(0xffffffffu, mx0, 1));
        mx0 = fmaxf(mx0, __shfl_xor_sync(0xffffffffu, mx0, 2));
        mx1 = fmaxf(mx1, __shfl_xor_sync(0xffffffffu, mx1, 1));
        mx1 = fmaxf(mx1, __shfl_xor_sync(0xffffffffu, mx1, 2));

        float mn0 = fmaxf(m0, mx0), mn1 = fmaxf(m1, mx1);
        float corr0 = __expf(m0 - mn0), corr1 = __expf(m1 - mn1);
        m0 = mn0; m1 = mn1;

        float s0 = 0.f, s1 = 0.f;
        #pragma unroll
        for (int j = 0; j < 8; j++) {
            float p0 = __expf(sacc[j][0] - mn0);
            float p1 = __expf(sacc[j][1] - mn0);
            float p2 = __expf(sacc[j][2] - mn1);
            float p3 = __expf(sacc[j][3] - mn1);
            sacc[j][0] = p0; sacc[j][1] = p1; sacc[j][2] = p2; sacc[j][3] = p3;
            s0 += p0 + p1;  s1 += p2 + p3;
        }
        s0 += __shfl_xor_sync(0xffffffffu, s0, 1);
        s0 += __shfl_xor_sync(0xffffffffu, s0, 2);
        s1 += __shfl_xor_sync(0xffffffffu, s1, 1);
        s1 += __shfl_xor_sync(0xffffffffu, s1, 2);
        l0 = l0 * corr0 + s0;
        l1 = l1 * corr1 + s1;

        unsigned int pa[8], pb[8];
        #pragma unroll
        for (int j = 0; j < 8; j++) {
            o[j][0] *= corr0; o[j][1] *= corr0;
            o[j][2] *= corr1; o[j][3] *= corr1;
            pa[j] = pack_bf2(sacc[j][0], sacc[j][1]);
            pb[j] = pack_bf2(sacc[j][2], sacc[j][3]);
        }

        #pragma unroll
        for (int t = 0; t < 4; t++) {
            #pragma unroll
            for (int jdp = 0; jdp < 4; jdp++) {
                unsigned int v0, v1, v2, v3;
                unsigned int vaddr = sVb +
                    ((t * 16 + (lg & 1) * 8 + lr) * FSTR + jdp * 16 + (lg >> 1) * 8) * 2;
                LDSM4T(v0, v1, v2, v3, vaddr);
                MMA16816(o[2 * jdp],     pa[2*t], pb[2*t], pa[2*t+1], pb[2*t+1], v0, v1);
                MMA16816(o[2 * jdp + 1], pa[2*t], pb[2*t], pa[2*t+1], pb[2*t+1], v2, v3);
            }
        }
        __syncthreads();
        buf ^= 1;
    }

    float inv0 = 1.0f / l0, inv1 = 1.0f / l1;
    int r0 = w * 16 + (lane >> 2);
    int gq0 = q0 + r0, gq1 = gq0 + 8;
    #pragma unroll
    for (int jd = 0; jd < 8; jd++) {
        int col = h * DH + jd * 8 + c0;
        if (gq0 < n)
            *(unsigned int*)(ATT + (size_t)(tok0 + gq0) * DIM + col) =
                pack_bf2(o[jd][0] * inv0, o[jd][1] * inv0);
        if (gq1 < n)
            *(unsigned int*)(ATT + (size_t)(tok0 + gq1) * DIM + col) =
                pack_bf2(o[jd][2] * inv1, o[jd][3] * inv1);
    }
}

// ---------------------------------------------------------------------------
// Launch
// ---------------------------------------------------------------------------
extern "C" void kernel_launch(void* const* d_in, const int* in_sizes, int n_in,
                              void* d_out, int out_size)
{
    const float* x0     = (const float*)d_in[0];
    const float* x1     = (const float*)d_in[1];
    const float* ln1_g  = (const float*)d_in[2];
    const float* ln1_b  = (const float*)d_in[3];
    const float* qkv_w  = (const float*)d_in[4];
    const float* qkv_b  = (const float*)d_in[5];
    const float* proj_w = (const float*)d_in[6];
    const float* proj_b = (const float*)d_in[7];
    const float* ls1    = (const float*)d_in[8];
    const float* ln2_g  = (const float*)d_in[9];
    const float* ln2_b  = (const float*)d_in[10];
    const float* fc1_w  = (const float*)d_in[11];
    const float* fc1_b  = (const float*)d_in[12];
    const float* fc2_w  = (const float*)d_in[13];
    const float* fc2_b  = (const float*)d_in[14];
    const float* ls2    = (const float*)d_in[15];

    void *pX, *pH, *pQKVb, *pYb, *pATTb, *pGb, *pWb;
    cudaGetSymbolAddress(&pX,    g_X);
    cudaGetSymbolAddress(&pH,    g_H);
    cudaGetSymbolAddress(&pQKVb, g_QKVb);
    cudaGetSymbolAddress(&pYb,   g_Yb);
    cudaGetSymbolAddress(&pATTb, g_ATTb);
    cudaGetSymbolAddress(&pGb,   g_Gb);
    cudaGetSymbolAddress(&pWb,   g_Wb);
    float* X   = (float*)pX;
    float* H   = (float*)pH;
    __nv_bfloat16* QKVb = (__nv_bfloat16*)pQKVb;
    __nv_bfloat16* Yb   = (__nv_bfloat16*)pYb;
    __nv_bfloat16* ATTb = (__nv_bfloat16*)pATTb;
    __nv_bfloat16* Gb   = (__nv_bfloat16*)pGb;
    __nv_bfloat16* Wb   = (__nv_bfloat16*)pWb;
    float* OUT = (float*)d_out;

    const int mTiles = (TT + 127) / 128;   // 59

    // raise dynamic smem limits (host-side, graph-capture safe)
    cudaFuncSetAttribute(bgemm_kernel<0, __nv_bfloat16>,
                         cudaFuncAttributeMaxDynamicSharedMemorySize, GEMM_SMEM_BYTES);
    cudaFuncSetAttribute(bgemm_kernel<1, float>,
                         cudaFuncAttributeMaxDynamicSharedMemorySize, GEMM_SMEM_BYTES);
    cudaFuncSetAttribute(bgemm_kernel<2, __nv_bfloat16>,
                         cudaFuncAttributeMaxDynamicSharedMemorySize, GEMM_SMEM_BYTES);

    // 0. weight conversion fp32 -> bf16
    {
        int n;
        n = DIM * 3 * DIM / 4; f2b_kernel<<<(n + 255) / 256, 256>>>(qkv_w,  Wb + WOFF_QKV,  n);
        n = DIM * DIM / 4;     f2b_kernel<<<(n + 255) / 256, 256>>>(proj_w, Wb + WOFF_PROJ, n);
        n = DIM * HID / 4;     f2b_kernel<<<(n + 255) / 256, 256>>>(fc1_w,  Wb + WOFF_FC1,  n);
        n = HID * DIM / 4;     f2b_kernel<<<(n + 255) / 256, 256>>>(fc2_w,  Wb + WOFF_FC2,  n);
    }

    // 1. pack x0 | x1 -> X
    {
        int n4a = T0 * DIM / 4, n4b = T1 * DIM / 4;
        copy4_kernel<<<(n4a + 255) / 256, 256>>>(x0, X, n4a);
        copy4_kernel<<<(n4b + 255) / 256, 256>>>(x1, X + (size_t)T0 * DIM, n4b);
    }

    // 2. LN1
    ln_kernel<<<TT, 256>>>(X, ln1_g, ln1_b, Yb);

    // 3. QKV (bf16 out)
    bgemm_kernel<0, __nv_bfloat16><<<dim3(3 * DIM / 128, mTiles), 128, GEMM_SMEM_BYTES>>>(
        Yb, Wb + WOFF_QKV, qkv_b, nullptr, nullptr, QKVb, TT, 3 * DIM, DIM);

    // 4. attention
    attn_kernel<<<dim3(NQB, NH), 128>>>(QKVb, ATTb);

    // 5. H = X + ls1 * (ATT @ proj_w + proj_b)
    bgemm_kernel<1, float><<<dim3(DIM / 128, mTiles), 128, GEMM_SMEM_BYTES>>>(
        ATTb, Wb + WOFF_PROJ, proj_b, X, ls1, H, TT, DIM, DIM);

    // 6. LN2
    ln_kernel<<<TT, 256>>>(H, ln2_g, ln2_b, Yb);

    // 7. Gb = gelu(Yb @ fc1_w + fc1_b)
    bgemm_kernel<2, __nv_bfloat16><<<dim3(HID / 128, mTiles), 128, GEMM_SMEM_BYTES>>>(
        Yb, Wb + WOFF_FC1, fc1_b, nullptr, nullptr, Gb, TT, HID, DIM);

    // 8. OUT = H + ls2 * (Gb @ fc2_w + fc2_b)
    bgemm_kernel<1, float><<<dim3(DIM / 128, mTiles), 128, GEMM_SMEM_BYTES>>>(
        Gb, Wb + WOFF_FC2, fc2_b, H, ls2, OUT, TT, DIM, HID);
}